// round 7
// baseline (speedup 1.0000x reference)
#include <cuda_runtime.h>
#include <math.h>

// Problem constants (fixed by the dataset)
#define N_NODES   8192
#define N_EDGES   262144
#define BS_NODES  4096
#define N_SEND    2048
#define ZSTRIDE   18         // 2 * (K+1)

#define IC        1024       // senders staged per unit
#define N_UNITS   512        // 8 seg * 32 j-tiles * 2 i-chunks
#define N_PARTS   (N_UNITS * 8)  // one slot per (unit, warp)
#define INT_GRID  592        // 4 * 148 SMs; dynamic stealing absorbs imbalance
#define FLT_BLOCKS 256

__device__ float g_int_part[N_PARTS];
__device__ float g_flt_part[FLT_BLOCKS];
__device__ float g_prior;
__device__ unsigned int g_unit_ctr = 0;

// ---------------------------------------------------------------------------
// Packed fp32 (f32x2) helpers
// ---------------------------------------------------------------------------
typedef unsigned long long u64_t;
union F2U { float2 f; u64_t u; };

__device__ __forceinline__ u64_t f2u(float2 v) { F2U x; x.f = v; return x.u; }
__device__ __forceinline__ float2 u2f(u64_t v) { F2U x; x.u = v; return x.f; }

__device__ __forceinline__ float2 fma2(float2 a, float2 b, float2 c) {
    u64_t d;
    asm("fma.rn.f32x2 %0, %1, %2, %3;"
        : "=l"(d) : "l"(f2u(a)), "l"(f2u(b)), "l"(f2u(c)));
    return u2f(d);
}
__device__ __forceinline__ float2 mul2(float2 a, float2 b) {
    u64_t d;
    asm("mul.rn.f32x2 %0, %1, %2;" : "=l"(d) : "l"(f2u(a)), "l"(f2u(b)));
    return u2f(d);
}
__device__ __forceinline__ float2 add2(float2 a, float2 b) {
    u64_t d;
    asm("add.rn.f32x2 %0, %1, %2;" : "=l"(d) : "l"(f2u(a)), "l"(f2u(b)));
    return u2f(d);
}
__device__ __forceinline__ float2 neg2(float2 a) {
    F2U x; x.f = a; x.u ^= 0x8000000080000000ULL; return x.f;
}
__device__ __forceinline__ float2 abs2(float2 a) {
    F2U x; x.f = a; x.u &= 0x7FFFFFFF7FFFFFFFULL; return x.f;
}
__device__ __forceinline__ float2 sub2(float2 a, float2 b) { return add2(a, neg2(b)); }
__device__ __forceinline__ float2 splat2(float v) { return make_float2(v, v); }
#define FZERO splat2(0.0f)

__device__ __forceinline__ float fast_rsqrt(float x) {
    float r; asm("rsqrt.approx.f32 %0, %1;" : "=f"(r) : "f"(x)); return r;
}
__device__ __forceinline__ float fast_ex2(float x) {
    float r; asm("ex2.approx.f32 %0, %1;" : "=f"(r) : "f"(x)); return r;
}
__device__ __forceinline__ float fast_rcp(float x) {
    float r; asm("rcp.approx.f32 %0, %1;" : "=f"(r) : "f"(x)); return r;
}

// ---------------------------------------------------------------------------
// Integral kernel: dynamic work-stealing over 512 big units.
// Unit = (segment k, j-tile of 256 nodes, i-chunk of 1024 senders).
// Thread owns one j; inner loop is f32x2 over sender pairs (512 iters/unit).
// Per-unit result written per WARP (shfl reduction, no block sync) so the
// final fixed-order sum is bitwise deterministic under any stealing order.
//
// Identities (w = Zs0 - Zr0, v = DZs - DZr):
//   D = |w|^2, S = |v|^2, C = -(v . w)
// Diagonal (sender == receiver) gives exactly D = S = 0 -> masked via
// D*S > 0. e = S*mu^2 - D <= 0 by Cauchy-Schwarz (no exp overflow).
// erf via Abramowitz-Stegun 7.1.25 (|err| <= 2.5e-5); the two reciprocals
// share a single rcp: 1/q1 = q2*rcp(q1*q2), 1/q2 = q1*rcp(q1*q2).
// ---------------------------------------------------------------------------
__global__ void __launch_bounds__(256)
integral_kernel(const float* __restrict__ Z,
                const int*   __restrict__ su,
                const float* __restrict__ cp)
{
    __shared__ __align__(16) float sA0[IC], sA1[IC], sD0[IC], sD1[IC];
    __shared__ int s_unit;

    const int tid  = threadIdx.x;
    const int wid  = tid >> 5;
    const int lane = tid & 31;

    const float2 ONE  = splat2(1.0f);
    const float2 L2E  = splat2( 1.4426950408889634f);
    const float2 NL2E = splat2(-1.4426950408889634f);
    const float2 PP   = splat2(0.47047f);
    // negated A&S 7.1.25 coefficients: g = ((B3 t + B2) t + B1) t,
    // erf(|x|) = 1 + g * exp(-x^2)
    const float2 B3 = splat2(-0.7478556f);
    const float2 B2 = splat2( 0.0958798f);
    const float2 B1 = splat2(-0.3480242f);

    for (;;) {
        __syncthreads();
        if (tid == 0) s_unit = (int)atomicAdd(&g_unit_ctr, 1u);
        __syncthreads();
        const int u = s_unit;
        if (u >= N_UNITS) break;

        const int k   = u >> 6;        // 0..7
        const int rem = u & 63;
        const int jt  = rem >> 1;      // 0..31
        const int ic  = rem & 1;       // 0..1

        // Receiver params (register, splatted to both f32x2 halves)
        const int j = jt * 256 + tid;
        const float* zr = Z + j * ZSTRIDE;
        const float r0  = zr[k];
        const float rn0 = zr[k + 1];
        const float r1  = zr[9 + k];
        const float rn1 = zr[9 + k + 1];
        const float2 R0  = splat2(r0);
        const float2 R1  = splat2(r1);
        const float2 DR0 = splat2(rn0 - r0);
        const float2 DR1 = splat2(rn1 - r1);

        // Stage 1024 senders (4 per thread)
        #pragma unroll
        for (int ii = tid; ii < IC; ii += 256) {
            const int sidx = su[ic * IC + ii];
            const float* zs = Z + sidx * ZSTRIDE;
            const float a0 = zs[k];
            const float b0 = zs[k + 1];
            const float a1 = zs[9 + k];
            const float b1 = zs[9 + k + 1];
            sA0[ii] = a0; sA1[ii] = a1;
            sD0[ii] = b0 - a0; sD1[ii] = b1 - a1;
        }
        __syncthreads();

        float2 acc = FZERO;
        #pragma unroll 4
        for (int i = 0; i < IC; i += 2) {
            const float2 A0  = *(const float2*)&sA0[i];
            const float2 A1  = *(const float2*)&sA1[i];
            const float2 Dz0 = *(const float2*)&sD0[i];
            const float2 Dz1 = *(const float2*)&sD1[i];

            // w = Zs0 - Zr0, v = DZs - DZr (exact 0 on the diagonal)
            const float2 w0 = sub2(A0, R0);
            const float2 w1 = sub2(A1, R1);
            const float2 v0 = sub2(Dz0, DR0);
            const float2 v1 = sub2(Dz1, DR1);

            const float2 Dv = fma2(w1, w1, mul2(w0, w0));
            const float2 Sv = fma2(v1, v1, mul2(v0, v0));
            const float2 nC = fma2(v1, w1, mul2(v0, w0));   // = v.w = -C

            float2 irs;
            irs.x = fast_rsqrt(Sv.x);
            irs.y = fast_rsqrt(Sv.y);

            const float2 sq   = mul2(Sv, irs);              // sqrt(S)
            const float2 ncir = mul2(nC, irs);              // -mu*sqrt(S)
            const float2 x1   = add2(sq, ncir);             // (1-mu)*sqrt(S)

            // ea = (ncir^2 - D) * l2e   (<= 0 by Cauchy-Schwarz)
            const float2 uu  = mul2(ncir, ncir);
            const float2 nDl = mul2(Dv, NL2E);
            const float2 ea  = fma2(uu, L2E, nDl);
            float2 ex;
            ex.x = fast_ex2(ea.x);
            ex.y = fast_ex2(ea.y);

            // --- erf(x1), erf(ncir) via A&S 7.1.25, shared rcp ---
            const float2 q1 = fma2(PP, abs2(x1),   ONE);
            const float2 q2 = fma2(PP, abs2(ncir), ONE);
            const float2 ab = mul2(q1, q2);
            float2 rr;
            rr.x = fast_rcp(ab.x);  rr.y = fast_rcp(ab.y);
            const float2 t1 = mul2(q2, rr);                 // 1/q1
            const float2 t2 = mul2(q1, rr);                 // 1/q2

            float2 g1 = fma2(B3, t1, B2);
            g1 = fma2(g1, t1, B1);
            g1 = mul2(g1, t1);
            float2 g2 = fma2(B3, t2, B2);
            g2 = fma2(g2, t2, B1);
            g2 = mul2(g2, t2);

            // exp(-x1^2), exp(-ncir^2) in log2 space
            const float2 x1sq = mul2(x1, x1);
            const float2 s1a  = mul2(x1sq, NL2E);
            const float2 s2b  = sub2(nDl, ea);              // = -ncir^2*l2e
            float2 E1, E2;
            E1.x = fast_ex2(s1a.x);  E1.y = fast_ex2(s1a.y);
            E2.x = fast_ex2(s2b.x);  E2.y = fast_ex2(s2b.y);

            float2 f1 = fma2(g1, E1, ONE);                  // erf(|x1|)
            float2 f2 = fma2(g2, E2, ONE);                  // erf(|ncir|)
            f1.x = copysignf(f1.x, x1.x);
            f1.y = copysignf(f1.y, x1.y);
            f2.x = copysignf(f2.x, ncir.x);
            f2.y = copysignf(f2.y, ncir.y);

            // erf(x1) + erf(cir) = erf(x1) - erf(ncir)
            const float2 es = sub2(f1, f2);
            const float2 vv = mul2(mul2(ex, es), irs);

            // mask: D*S > 0 (both >= 0; zero exactly on the diagonal)
            const float2 DS = mul2(Dv, Sv);
            float2 contrib;
            contrib.x = (DS.x > 0.0f) ? vv.x : 0.0f;
            contrib.y = (DS.y > 0.0f) ? vv.y : 0.0f;
            acc = add2(acc, contrib);
        }

        const float dt = cp[k + 1] - cp[k];
        // fold sigma's 1/sqrt(2), the cdf 0.5 and the scan 0.5: 0.25/sqrt(2)
        float tot = (acc.x + acc.y) * (dt * 0.17677669529663687f);

        // warp-level reduction (no block sync); one slot per (unit, warp)
        #pragma unroll
        for (int off = 16; off > 0; off >>= 1)
            tot += __shfl_down_sync(0xFFFFFFFFu, tot, off);
        if (lane == 0) g_int_part[u * 8 + wid] = tot;
    }
}

// ---------------------------------------------------------------------------
// flt kernel: per-edge interpolated similarity term
// ---------------------------------------------------------------------------
__global__ void __launch_bounds__(256)
flt_kernel(const float* __restrict__ Z,
           const float* __restrict__ ts,
           const int*   __restrict__ snd,
           const int*   __restrict__ rcv,
           const float* __restrict__ cp)
{
    const int tid     = threadIdx.x;
    const int gthread = blockIdx.x * 256 + tid;
    const int nthread = FLT_BLOCKS * 256;
    const float seg   = cp[1] - cp[0];

    float acc = 0.0f;
    for (int e = gthread; e < N_EDGES; e += nthread) {
        const float t  = ts[e];
        const float q  = t / seg;
        const float kf = floorf(q);
        const int   ka = (int)kf;
        const float d  = q - kf;
        const float od = 1.0f - d;

        const float* zs = Z + snd[e] * ZSTRIDE;
        const float* zr = Z + rcv[e] * ZSTRIDE;
        const float sc0 = zs[ka],     sn0 = zs[ka + 1];
        const float sc1 = zs[9 + ka], sn1 = zs[9 + ka + 1];
        const float rc0 = zr[ka],     rn0 = zr[ka + 1];
        const float rc1 = zr[9 + ka], rn1 = zr[9 + ka + 1];

        const float scrc = sc0 * rc0 + sc1 * rc1;
        const float scsc = sc0 * sc0 + sc1 * sc1;
        const float rcrc = rc0 * rc0 + rc1 * rc1;
        const float scrn = sc0 * rn0 + sc1 * rn1;
        const float snrc = sn0 * rc0 + sn1 * rc1;
        const float scsn = sc0 * sn0 + sc1 * sn1;
        const float rcrn = rc0 * rn0 + rc1 * rn1;
        const float snrn = sn0 * rn0 + sn1 * rn1;
        const float snsn = sn0 * sn0 + sn1 * sn1;
        const float rnrn = rn0 * rn0 + rn1 * rn1;

        const float flt = od * od * (2.0f * scrc - scsc - rcrc)
                        + 2.0f * d * od * (scrn + snrc - scsn - rcrn)
                        + d * d * (2.0f * snrn - snsn - rnrn);
        acc += flt;
    }

    __shared__ float red[256];
    red[tid] = acc;
    __syncthreads();
    for (int s = 128; s > 0; s >>= 1) {
        if (tid < s) red[tid] += red[tid + s];
        __syncthreads();
    }
    if (tid == 0) g_flt_part[blockIdx.x] = red[0];
}

// ---------------------------------------------------------------------------
// prior kernel: gauss-markov prior over sampled nodes (1 block)
// ---------------------------------------------------------------------------
__global__ void __launch_bounds__(256)
prior_kernel(const float* __restrict__ Z, const int* __restrict__ nodes)
{
    const int tid = threadIdx.x;
    float acc = 0.0f;
    for (int m = tid; m < BS_NODES; m += 256) {
        const int n = nodes[m];
        const float* z = Z + n * ZSTRIDE;
        #pragma unroll
        for (int dim = 0; dim < 2; dim++) {
            const float* zd = z + dim * 9;
            float prev = zd[0];
            acc += prev * prev;
            #pragma unroll
            for (int kk = 1; kk <= 8; kk++) {
                const float cur = zd[kk];
                const float df  = cur - prev;
                acc += df * df;
                prev = cur;
            }
        }
    }
    __shared__ float red[256];
    red[tid] = acc;
    __syncthreads();
    for (int s = 128; s > 0; s >>= 1) {
        if (tid < s) red[tid] += red[tid + s];
        __syncthreads();
    }
    if (tid == 0) g_prior = red[0];
}

// ---------------------------------------------------------------------------
// Final combine (parallel, deterministic fixed-order reduction) + counter reset
// ---------------------------------------------------------------------------
__global__ void __launch_bounds__(256)
final_kernel(const float* __restrict__ beta_p, float* __restrict__ out)
{
    __shared__ float red[256];
    __shared__ float s_integral;
    const int tid = threadIdx.x;

    float s = 0.0f;
    #pragma unroll
    for (int i = tid; i < N_PARTS; i += 256) s += g_int_part[i];
    red[tid] = s;
    __syncthreads();
    for (int st = 128; st > 0; st >>= 1) {
        if (tid < st) red[tid] += red[tid + st];
        __syncthreads();
    }
    if (tid == 0) s_integral = red[0];
    __syncthreads();

    red[tid] = g_flt_part[tid];
    __syncthreads();
    for (int st = 128; st > 0; st >>= 1) {
        if (tid < st) red[tid] += red[tid + st];
        __syncthreads();
    }

    if (tid == 0) {
        const float flt      = red[0];
        const float integral = s_integral;
        const float beta     = beta_p[0];
        const float prior    = 10.0f * g_prior;              // PENALTY
        const float result   = 2.0f * (prior - beta * 262144.0f - flt
                                + 2.5066282746310002f * expf(beta) * integral);
        out[0] = result;
        g_unit_ctr = 0;   // reset work-stealing counter for the next call
    }
}

// ---------------------------------------------------------------------------
extern "C" void kernel_launch(void* const* d_in, const int* in_sizes, int n_in,
                              void* d_out, int out_size)
{
    const float* Z    = (const float*)d_in[0];
    const float* beta = (const float*)d_in[1];
    const float* ts   = (const float*)d_in[2];
    const int*   snd  = (const int*)d_in[3];
    const int*   rcv  = (const int*)d_in[4];
    const int*   nds  = (const int*)d_in[5];
    const int*   su   = (const int*)d_in[6];
    const float* cp   = (const float*)d_in[7];
    float* out = (float*)d_out;

    prior_kernel<<<1, 256>>>(Z, nds);
    flt_kernel<<<FLT_BLOCKS, 256>>>(Z, ts, snd, rcv, cp);
    integral_kernel<<<INT_GRID, 256>>>(Z, su, cp);
    final_kernel<<<1, 256>>>(beta, out);
}

// round 8
// speedup vs baseline: 1.3831x; 1.3831x over previous
#include <cuda_runtime.h>
#include <math.h>

// Problem constants (fixed by the dataset)
#define N_NODES   8192
#define N_EDGES   262144
#define BS_NODES  4096
#define N_SEND    2048
#define ZSTRIDE   18         // 2 * (K+1)

#define IC        256        // senders staged per unit
#define N_UNITS   2048       // 8 seg * 32 j-tiles * 8 i-chunks
#define N_PARTS   (N_UNITS * 8)
#define INT_GRID  592        // 4 * 148 SMs; dynamic stealing absorbs imbalance
#define FLT_BLOCKS 256

__device__ float g_int_part[N_PARTS];
__device__ float g_flt_part[FLT_BLOCKS];
__device__ float g_prior;
__device__ unsigned int g_unit_ctr = 0;

// ---------------------------------------------------------------------------
// Packed fp32 (f32x2) helpers
// ---------------------------------------------------------------------------
typedef unsigned long long u64_t;
union F2U { float2 f; u64_t u; };

__device__ __forceinline__ u64_t f2u(float2 v) { F2U x; x.f = v; return x.u; }
__device__ __forceinline__ float2 u2f(u64_t v) { F2U x; x.u = v; return x.f; }

__device__ __forceinline__ float2 fma2(float2 a, float2 b, float2 c) {
    u64_t d;
    asm("fma.rn.f32x2 %0, %1, %2, %3;"
        : "=l"(d) : "l"(f2u(a)), "l"(f2u(b)), "l"(f2u(c)));
    return u2f(d);
}
__device__ __forceinline__ float2 mul2(float2 a, float2 b) {
    u64_t d;
    asm("mul.rn.f32x2 %0, %1, %2;" : "=l"(d) : "l"(f2u(a)), "l"(f2u(b)));
    return u2f(d);
}
__device__ __forceinline__ float2 add2(float2 a, float2 b) {
    u64_t d;
    asm("add.rn.f32x2 %0, %1, %2;" : "=l"(d) : "l"(f2u(a)), "l"(f2u(b)));
    return u2f(d);
}
__device__ __forceinline__ float2 neg2(float2 a) {
    F2U x; x.f = a; x.u ^= 0x8000000080000000ULL; return x.f;
}
__device__ __forceinline__ float2 abs2(float2 a) {
    F2U x; x.f = a; x.u &= 0x7FFFFFFF7FFFFFFFULL; return x.f;
}
__device__ __forceinline__ float2 sub2(float2 a, float2 b) { return add2(a, neg2(b)); }
__device__ __forceinline__ float2 splat2(float v) { return make_float2(v, v); }
#define FZERO splat2(0.0f)

__device__ __forceinline__ float fast_rsqrt(float x) {
    float r; asm("rsqrt.approx.f32 %0, %1;" : "=f"(r) : "f"(x)); return r;
}
__device__ __forceinline__ float fast_ex2(float x) {
    float r; asm("ex2.approx.f32 %0, %1;" : "=f"(r) : "f"(x)); return r;
}

// log2(erfc(t)) for t >= 0, degree-5 odd-ish poly (njuffa-derived, top two
// terms dropped; |erf err| <= ~1.3e-4 worst, ~5e-5 typical). log2(e) folded
// into the coefficients so the result feeds ex2 directly.
__device__ __forceinline__ float2 log2_erfc(float2 t) {
    const float2 D5 = splat2(-5.603370e-3f);
    const float2 D4 = splat2( 3.499207e-2f);
    const float2 D3 = splat2(-1.540479e-1f);
    const float2 D2 = splat2(-9.158902e-1f);
    const float2 D1 = splat2(-1.6283940f);
    float2 q = fma2(D5, t, D4);
    q = fma2(q, t, D3);
    q = fma2(q, t, D2);
    q = fma2(q, t, D1);
    return mul2(q, t);
}

// ---------------------------------------------------------------------------
// Integral kernel: dynamic work-stealing over 2048 units.
// Unit = (segment k, j-tile of 256 nodes, i-chunk of 256 senders).
// Thread owns one j; inner loop is f32x2 over sender pairs.
// Output: one slot per (unit, warp) via shfl reduction — final fixed-order
// sum is bitwise deterministic under any stealing assignment.
//
// Identities (w = Zs0 - Zr0, v = DZs - DZr):
//   D = |w|^2, S = |v|^2, C = -(v . w)
// Sv is seeded with +1e-20 so the diagonal (sender == receiver, w=v=0
// exactly) flows through to contribution exactly 0 with NO mask:
//   irs finite, ncir=+0, x1~1e-10, E=1 -> es=0 -> vv=0.
// e = S*mu^2 - D <= 0 by Cauchy-Schwarz (no exp overflow).
// erf(x) = copysign(1 - exp2(log2_erfc(|x|)), x)  — no rcp needed.
// ---------------------------------------------------------------------------
__global__ void __launch_bounds__(256)
integral_kernel(const float* __restrict__ Z,
                const int*   __restrict__ su,
                const float* __restrict__ cp)
{
    __shared__ __align__(16) float sA0[IC], sA1[IC], sD0[IC], sD1[IC];
    __shared__ int s_unit;

    const int tid  = threadIdx.x;
    const int wid  = tid >> 5;
    const int lane = tid & 31;

    const float2 ONE  = splat2(1.0f);
    const float2 L2E  = splat2( 1.4426950408889634f);
    const float2 NL2E = splat2(-1.4426950408889634f);
    const float2 TINY = splat2(1e-20f);

    for (;;) {
        __syncthreads();
        if (tid == 0) s_unit = (int)atomicAdd(&g_unit_ctr, 1u);
        __syncthreads();
        const int u = s_unit;
        if (u >= N_UNITS) break;

        const int k   = u >> 8;        // 0..7
        const int rem = u & 255;
        const int jt  = rem >> 3;      // 0..31
        const int ic  = rem & 7;       // 0..7

        // Receiver params (register, splatted to both f32x2 halves)
        const int j = jt * 256 + tid;
        const float* zr = Z + j * ZSTRIDE;
        const float r0  = zr[k];
        const float rn0 = zr[k + 1];
        const float r1  = zr[9 + k];
        const float rn1 = zr[9 + k + 1];
        const float2 R0  = splat2(r0);
        const float2 R1  = splat2(r1);
        const float2 DR0 = splat2(rn0 - r0);
        const float2 DR1 = splat2(rn1 - r1);

        // Stage 256 senders (one per thread)
        {
            const int sidx = su[ic * IC + tid];
            const float* zs = Z + sidx * ZSTRIDE;
            const float a0 = zs[k];
            const float b0 = zs[k + 1];
            const float a1 = zs[9 + k];
            const float b1 = zs[9 + k + 1];
            sA0[tid] = a0; sA1[tid] = a1;
            sD0[tid] = b0 - a0; sD1[tid] = b1 - a1;
        }
        __syncthreads();

        float2 acc = FZERO;
        #pragma unroll 4
        for (int i = 0; i < IC; i += 2) {
            const float2 A0  = *(const float2*)&sA0[i];
            const float2 A1  = *(const float2*)&sA1[i];
            const float2 Dz0 = *(const float2*)&sD0[i];
            const float2 Dz1 = *(const float2*)&sD1[i];

            // w = Zs0 - Zr0, v = DZs - DZr (exact 0 on the diagonal)
            const float2 w0 = sub2(A0, R0);
            const float2 w1 = sub2(A1, R1);
            const float2 v0 = sub2(Dz0, DR0);
            const float2 v1 = sub2(Dz1, DR1);

            const float2 Dv = fma2(w1, w1, mul2(w0, w0));
            const float2 Sv = fma2(v1, v1, fma2(v0, v0, TINY));
            const float2 nC = fma2(v1, w1, mul2(v0, w0));   // = v.w = -C

            float2 irs;
            irs.x = fast_rsqrt(Sv.x);
            irs.y = fast_rsqrt(Sv.y);

            const float2 sq   = mul2(Sv, irs);              // sqrt(S)
            const float2 ncir = mul2(nC, irs);              // -mu*sqrt(S)
            const float2 x1   = add2(sq, ncir);             // (1-mu)*sqrt(S)

            // ea = (ncir^2 - D) * l2e   (<= 0 by Cauchy-Schwarz)
            const float2 uu  = mul2(ncir, ncir);
            const float2 nDl = mul2(Dv, NL2E);
            const float2 ea  = fma2(uu, L2E, nDl);
            float2 ex;
            ex.x = fast_ex2(ea.x);
            ex.y = fast_ex2(ea.y);

            // erf via single-path log2(erfc) poly
            const float2 p1 = log2_erfc(abs2(x1));
            const float2 p2 = log2_erfc(abs2(ncir));
            float2 E1, E2;
            E1.x = fast_ex2(p1.x);  E1.y = fast_ex2(p1.y);
            E2.x = fast_ex2(p2.x);  E2.y = fast_ex2(p2.y);
            const float2 F1 = sub2(ONE, E1);                // erf(|x1|)
            const float2 F2 = sub2(ONE, E2);                // erf(|ncir|)
            float2 f1, f2;
            f1.x = copysignf(F1.x, x1.x);
            f1.y = copysignf(F1.y, x1.y);
            f2.x = copysignf(F2.x, ncir.x);
            f2.y = copysignf(F2.y, ncir.y);

            // erf(x1) + erf(cir) = erf(x1) - erf(ncir)
            const float2 es = sub2(f1, f2);
            const float2 vv = mul2(mul2(ex, es), irs);
            acc = add2(acc, vv);
        }

        const float dt = cp[k + 1] - cp[k];
        // fold sigma's 1/sqrt(2), the cdf 0.5 and the scan 0.5: 0.25/sqrt(2)
        float tot = (acc.x + acc.y) * (dt * 0.17677669529663687f);

        // warp-level reduction; one slot per (unit, warp)
        #pragma unroll
        for (int off = 16; off > 0; off >>= 1)
            tot += __shfl_down_sync(0xFFFFFFFFu, tot, off);
        if (lane == 0) g_int_part[u * 8 + wid] = tot;
    }
}

// ---------------------------------------------------------------------------
// flt kernel: per-edge interpolated similarity term
// ---------------------------------------------------------------------------
__global__ void __launch_bounds__(256)
flt_kernel(const float* __restrict__ Z,
           const float* __restrict__ ts,
           const int*   __restrict__ snd,
           const int*   __restrict__ rcv,
           const float* __restrict__ cp)
{
    const int tid     = threadIdx.x;
    const int gthread = blockIdx.x * 256 + tid;
    const int nthread = FLT_BLOCKS * 256;
    const float seg   = cp[1] - cp[0];

    float acc = 0.0f;
    for (int e = gthread; e < N_EDGES; e += nthread) {
        const float t  = ts[e];
        const float q  = t / seg;
        const float kf = floorf(q);
        const int   ka = (int)kf;
        const float d  = q - kf;
        const float od = 1.0f - d;

        const float* zs = Z + snd[e] * ZSTRIDE;
        const float* zr = Z + rcv[e] * ZSTRIDE;
        const float sc0 = zs[ka],     sn0 = zs[ka + 1];
        const float sc1 = zs[9 + ka], sn1 = zs[9 + ka + 1];
        const float rc0 = zr[ka],     rn0 = zr[ka + 1];
        const float rc1 = zr[9 + ka], rn1 = zr[9 + ka + 1];

        const float scrc = sc0 * rc0 + sc1 * rc1;
        const float scsc = sc0 * sc0 + sc1 * sc1;
        const float rcrc = rc0 * rc0 + rc1 * rc1;
        const float scrn = sc0 * rn0 + sc1 * rn1;
        const float snrc = sn0 * rc0 + sn1 * rc1;
        const float scsn = sc0 * sn0 + sc1 * sn1;
        const float rcrn = rc0 * rn0 + rc1 * rn1;
        const float snrn = sn0 * rn0 + sn1 * rn1;
        const float snsn = sn0 * sn0 + sn1 * sn1;
        const float rnrn = rn0 * rn0 + rn1 * rn1;

        const float flt = od * od * (2.0f * scrc - scsc - rcrc)
                        + 2.0f * d * od * (scrn + snrc - scsn - rcrn)
                        + d * d * (2.0f * snrn - snsn - rnrn);
        acc += flt;
    }

    __shared__ float red[256];
    red[tid] = acc;
    __syncthreads();
    for (int s = 128; s > 0; s >>= 1) {
        if (tid < s) red[tid] += red[tid + s];
        __syncthreads();
    }
    if (tid == 0) g_flt_part[blockIdx.x] = red[0];
}

// ---------------------------------------------------------------------------
// prior kernel: gauss-markov prior over sampled nodes (1 block)
// ---------------------------------------------------------------------------
__global__ void __launch_bounds__(256)
prior_kernel(const float* __restrict__ Z, const int* __restrict__ nodes)
{
    const int tid = threadIdx.x;
    float acc = 0.0f;
    for (int m = tid; m < BS_NODES; m += 256) {
        const int n = nodes[m];
        const float* z = Z + n * ZSTRIDE;
        #pragma unroll
        for (int dim = 0; dim < 2; dim++) {
            const float* zd = z + dim * 9;
            float prev = zd[0];
            acc += prev * prev;
            #pragma unroll
            for (int kk = 1; kk <= 8; kk++) {
                const float cur = zd[kk];
                const float df  = cur - prev;
                acc += df * df;
                prev = cur;
            }
        }
    }
    __shared__ float red[256];
    red[tid] = acc;
    __syncthreads();
    for (int s = 128; s > 0; s >>= 1) {
        if (tid < s) red[tid] += red[tid + s];
        __syncthreads();
    }
    if (tid == 0) g_prior = red[0];
}

// ---------------------------------------------------------------------------
// Final combine (parallel, deterministic fixed-order reduction) + counter reset
// ---------------------------------------------------------------------------
__global__ void __launch_bounds__(256)
final_kernel(const float* __restrict__ beta_p, float* __restrict__ out)
{
    __shared__ float red[256];
    __shared__ float s_integral;
    const int tid = threadIdx.x;

    float s = 0.0f;
    #pragma unroll
    for (int i = tid; i < N_PARTS; i += 256) s += g_int_part[i];
    red[tid] = s;
    __syncthreads();
    for (int st = 128; st > 0; st >>= 1) {
        if (tid < st) red[tid] += red[tid + st];
        __syncthreads();
    }
    if (tid == 0) s_integral = red[0];
    __syncthreads();

    red[tid] = g_flt_part[tid];
    __syncthreads();
    for (int st = 128; st > 0; st >>= 1) {
        if (tid < st) red[tid] += red[tid + st];
        __syncthreads();
    }

    if (tid == 0) {
        const float flt      = red[0];
        const float integral = s_integral;
        const float beta     = beta_p[0];
        const float prior    = 10.0f * g_prior;              // PENALTY
        const float result   = 2.0f * (prior - beta * 262144.0f - flt
                                + 2.5066282746310002f * expf(beta) * integral);
        out[0] = result;
        g_unit_ctr = 0;   // reset work-stealing counter for the next call
    }
}

// ---------------------------------------------------------------------------
extern "C" void kernel_launch(void* const* d_in, const int* in_sizes, int n_in,
                              void* d_out, int out_size)
{
    const float* Z    = (const float*)d_in[0];
    const float* beta = (const float*)d_in[1];
    const float* ts   = (const float*)d_in[2];
    const int*   snd  = (const int*)d_in[3];
    const int*   rcv  = (const int*)d_in[4];
    const int*   nds  = (const int*)d_in[5];
    const int*   su   = (const int*)d_in[6];
    const float* cp   = (const float*)d_in[7];
    float* out = (float*)d_out;

    prior_kernel<<<1, 256>>>(Z, nds);
    flt_kernel<<<FLT_BLOCKS, 256>>>(Z, ts, snd, rcv, cp);
    integral_kernel<<<INT_GRID, 256>>>(Z, su, cp);
    final_kernel<<<1, 256>>>(beta, out);
}

// round 9
// speedup vs baseline: 1.5012x; 1.0854x over previous
#include <cuda_runtime.h>
#include <math.h>

// Problem constants (fixed by the dataset)
#define N_NODES   8192
#define N_EDGES   262144
#define BS_NODES  4096
#define N_SEND    2048
#define ZSTRIDE   18         // 2 * (K+1)

#define IC        256        // senders staged per integral unit
#define U_INT     2048       // 8 seg * 32 j-tiles * 8 i-chunks
#define U_FLT     64         // 4096 edges each
#define U_ALL     (U_INT + U_FLT + 1)   // + 1 prior unit
#define N_PARTS   (U_ALL * 8)           // one slot per (unit, warp)
#define GRID      592        // 4 * 148 SMs; dynamic stealing absorbs imbalance

__device__ float g_part[N_PARTS];
__device__ unsigned int g_unit_ctr = 0;

// ---------------------------------------------------------------------------
// Packed fp32 (f32x2) helpers
// ---------------------------------------------------------------------------
typedef unsigned long long u64_t;
union F2U { float2 f; u64_t u; };

__device__ __forceinline__ u64_t f2u(float2 v) { F2U x; x.f = v; return x.u; }
__device__ __forceinline__ float2 u2f(u64_t v) { F2U x; x.u = v; return x.f; }

__device__ __forceinline__ float2 fma2(float2 a, float2 b, float2 c) {
    u64_t d;
    asm("fma.rn.f32x2 %0, %1, %2, %3;"
        : "=l"(d) : "l"(f2u(a)), "l"(f2u(b)), "l"(f2u(c)));
    return u2f(d);
}
__device__ __forceinline__ float2 mul2(float2 a, float2 b) {
    u64_t d;
    asm("mul.rn.f32x2 %0, %1, %2;" : "=l"(d) : "l"(f2u(a)), "l"(f2u(b)));
    return u2f(d);
}
__device__ __forceinline__ float2 add2(float2 a, float2 b) {
    u64_t d;
    asm("add.rn.f32x2 %0, %1, %2;" : "=l"(d) : "l"(f2u(a)), "l"(f2u(b)));
    return u2f(d);
}
__device__ __forceinline__ float2 neg2(float2 a) {
    F2U x; x.f = a; x.u ^= 0x8000000080000000ULL; return x.f;
}
__device__ __forceinline__ float2 abs2(float2 a) {
    F2U x; x.f = a; x.u &= 0x7FFFFFFF7FFFFFFFULL; return x.f;
}
__device__ __forceinline__ float2 sub2(float2 a, float2 b) { return add2(a, neg2(b)); }
__device__ __forceinline__ float2 splat2(float v) { return make_float2(v, v); }
#define FZERO splat2(0.0f)

__device__ __forceinline__ float fast_rsqrt(float x) {
    float r; asm("rsqrt.approx.f32 %0, %1;" : "=f"(r) : "f"(x)); return r;
}
__device__ __forceinline__ float fast_ex2(float x) {
    float r; asm("ex2.approx.f32 %0, %1;" : "=f"(r) : "f"(x)); return r;
}

// log2(erfc(t)) for t >= 0, degree-5 poly (njuffa-derived, log2(e) folded in;
// |erf err| <= ~1.3e-4 worst case). Same poly as the R8-verified version.
__device__ __forceinline__ float2 log2_erfc(float2 t) {
    const float2 D5 = splat2(-5.603370e-3f);
    const float2 D4 = splat2( 3.499207e-2f);
    const float2 D3 = splat2(-1.540479e-1f);
    const float2 D2 = splat2(-9.158902e-1f);
    const float2 D1 = splat2(-1.6283940f);
    float2 q = fma2(D5, t, D4);
    q = fma2(q, t, D3);
    q = fma2(q, t, D2);
    q = fma2(q, t, D1);
    return mul2(q, t);
}

// ---------------------------------------------------------------------------
// Fused kernel: one dynamic work-stealing pool over
//   units [0, U_INT):           integral (seg k, 256-j tile, 256-i chunk)
//   units [U_INT, U_INT+U_FLT): flt, 4096 edges each
//   unit  U_ALL-1:              prior
// Every unit writes per-(unit,warp) partials -> final fixed-order sum is
// bitwise deterministic regardless of which block ran which unit.
//
// Integral identities (w = Zs0-Zr0, v = DZs-DZr): D=|w|^2, S=|v|^2, C=-(v.w).
// Sv seeded with +1e-20 so the diagonal flows to exactly 0 with no mask
// (verified: ea=-0, q1=p1=-1.63e-10 -> exp2 == exp2(ea) -> terms == 0).
// e = S*mu^2 - D <= 0 by Cauchy-Schwarz. erf evaluated as
//   ex - exp2(ea + log2_erfc(|x|))  (>= 0), sign applied via packed OR.
// ---------------------------------------------------------------------------
__global__ void __launch_bounds__(256)
fused_kernel(const float* __restrict__ Z,
             const int*   __restrict__ su,
             const float* __restrict__ cp,
             const float* __restrict__ ts,
             const int*   __restrict__ snd,
             const int*   __restrict__ rcv,
             const int*   __restrict__ nodes)
{
    __shared__ __align__(16) float sA0[IC], sA1[IC], sD0[IC], sD1[IC];
    __shared__ int s_unit;

    const int tid  = threadIdx.x;
    const int wid  = tid >> 5;
    const int lane = tid & 31;

    const float2 L2E  = splat2( 1.4426950408889634f);
    const float2 NL2E = splat2(-1.4426950408889634f);
    const float2 TINY = splat2(1e-20f);
    const u64_t  SGN  = 0x8000000080000000ULL;

    for (;;) {
        __syncthreads();
        if (tid == 0) s_unit = (int)atomicAdd(&g_unit_ctr, 1u);
        __syncthreads();
        const int u = s_unit;
        if (u >= U_ALL) break;

        if (u < U_INT) {
            // ---------------- integral unit ----------------
            const int k   = u >> 8;        // 0..7
            const int rem = u & 255;
            const int jt  = rem >> 3;      // 0..31
            const int ic  = rem & 7;       // 0..7

            const int j = jt * 256 + tid;
            const float* zr = Z + j * ZSTRIDE;
            const float r0  = zr[k];
            const float rn0 = zr[k + 1];
            const float r1  = zr[9 + k];
            const float rn1 = zr[9 + k + 1];
            const float2 R0  = splat2(r0);
            const float2 R1  = splat2(r1);
            const float2 DR0 = splat2(rn0 - r0);
            const float2 DR1 = splat2(rn1 - r1);

            {
                const int sidx = su[ic * IC + tid];
                const float* zs = Z + sidx * ZSTRIDE;
                const float a0 = zs[k];
                const float b0 = zs[k + 1];
                const float a1 = zs[9 + k];
                const float b1 = zs[9 + k + 1];
                sA0[tid] = a0; sA1[tid] = a1;
                sD0[tid] = b0 - a0; sD1[tid] = b1 - a1;
            }
            __syncthreads();

            float2 acc = FZERO;
            #pragma unroll 4
            for (int i = 0; i < IC; i += 2) {
                const float2 A0  = *(const float2*)&sA0[i];
                const float2 A1  = *(const float2*)&sA1[i];
                const float2 Dz0 = *(const float2*)&sD0[i];
                const float2 Dz1 = *(const float2*)&sD1[i];

                const float2 w0 = sub2(A0, R0);
                const float2 w1 = sub2(A1, R1);
                const float2 v0 = sub2(Dz0, DR0);
                const float2 v1 = sub2(Dz1, DR1);

                const float2 Dv = fma2(w1, w1, mul2(w0, w0));
                const float2 Sv = fma2(v1, v1, fma2(v0, v0, TINY));
                const float2 nC = fma2(v1, w1, mul2(v0, w0));

                float2 irs;
                irs.x = fast_rsqrt(Sv.x);
                irs.y = fast_rsqrt(Sv.y);

                const float2 ncir = mul2(nC, irs);           // -mu*sqrt(S)
                const float2 x1   = fma2(Sv, irs, ncir);     // (1-mu)*sqrt(S)

                // ea = (ncir^2 - D)*l2e  (<= 0)
                const float2 uu  = mul2(ncir, ncir);
                const float2 nDl = mul2(Dv, NL2E);
                const float2 ea  = fma2(uu, L2E, nDl);

                const float2 p1 = log2_erfc(abs2(x1));
                const float2 p2 = log2_erfc(abs2(ncir));
                const float2 q1 = add2(ea, p1);
                const float2 q2 = add2(ea, p2);

                float2 ex, G1, G2;
                ex.x = fast_ex2(ea.x);  ex.y = fast_ex2(ea.y);
                G1.x = fast_ex2(q1.x);  G1.y = fast_ex2(q1.y);
                G2.x = fast_ex2(q2.x);  G2.y = fast_ex2(q2.y);

                // term = ex*erf(|.|) >= 0; apply sign via packed OR
                const float2 t1 = sub2(ex, G1);
                const float2 t2 = sub2(ex, G2);
                const float2 u1 = u2f(f2u(t1) | (f2u(x1)   & SGN));
                const float2 v2 = u2f(f2u(t2) | (f2u(ncir) & SGN));

                // ex*(erf(x1) + erf(cir)) = u1 - v2
                const float2 es = sub2(u1, v2);
                acc = fma2(es, irs, acc);
            }

            const float dt = cp[k + 1] - cp[k];
            // fold sigma's 1/sqrt(2), the cdf 0.5 and the scan 0.5
            float tot = (acc.x + acc.y) * (dt * 0.17677669529663687f);
            #pragma unroll
            for (int off = 16; off > 0; off >>= 1)
                tot += __shfl_down_sync(0xFFFFFFFFu, tot, off);
            if (lane == 0) g_part[u * 8 + wid] = tot;

        } else if (u < U_INT + U_FLT) {
            // ---------------- flt unit (4096 edges) ----------------
            const int base = (u - U_INT) * 4096;
            const float seg = cp[1] - cp[0];

            float acc = 0.0f;
            #pragma unroll 4
            for (int r = 0; r < 16; r++) {
                const int e = base + r * 256 + tid;
                const float t  = ts[e];
                const float q  = t / seg;
                const float kf = floorf(q);
                const int   ka = (int)kf;
                const float d  = q - kf;
                const float od = 1.0f - d;

                const float* zs = Z + snd[e] * ZSTRIDE;
                const float* zr = Z + rcv[e] * ZSTRIDE;
                const float sc0 = zs[ka],     sn0 = zs[ka + 1];
                const float sc1 = zs[9 + ka], sn1 = zs[9 + ka + 1];
                const float rc0 = zr[ka],     rn0 = zr[ka + 1];
                const float rc1 = zr[9 + ka], rn1 = zr[9 + ka + 1];

                const float scrc = sc0 * rc0 + sc1 * rc1;
                const float scsc = sc0 * sc0 + sc1 * sc1;
                const float rcrc = rc0 * rc0 + rc1 * rc1;
                const float scrn = sc0 * rn0 + sc1 * rn1;
                const float snrc = sn0 * rc0 + sn1 * rc1;
                const float scsn = sc0 * sn0 + sc1 * sn1;
                const float rcrn = rc0 * rn0 + rc1 * rn1;
                const float snrn = sn0 * rn0 + sn1 * rn1;
                const float snsn = sn0 * sn0 + sn1 * sn1;
                const float rnrn = rn0 * rn0 + rn1 * rn1;

                acc += od * od * (2.0f * scrc - scsc - rcrc)
                     + 2.0f * d * od * (scrn + snrc - scsn - rcrn)
                     + d * d * (2.0f * snrn - snsn - rnrn);
            }
            #pragma unroll
            for (int off = 16; off > 0; off >>= 1)
                acc += __shfl_down_sync(0xFFFFFFFFu, acc, off);
            if (lane == 0) g_part[u * 8 + wid] = acc;

        } else {
            // ---------------- prior unit (4096 nodes) ----------------
            float acc = 0.0f;
            #pragma unroll
            for (int r = 0; r < 16; r++) {
                const int n = nodes[r * 256 + tid];
                const float* z = Z + n * ZSTRIDE;
                #pragma unroll
                for (int dim = 0; dim < 2; dim++) {
                    const float* zd = z + dim * 9;
                    float prev = zd[0];
                    acc += prev * prev;
                    #pragma unroll
                    for (int kk = 1; kk <= 8; kk++) {
                        const float cur = zd[kk];
                        const float df  = cur - prev;
                        acc += df * df;
                        prev = cur;
                    }
                }
            }
            #pragma unroll
            for (int off = 16; off > 0; off >>= 1)
                acc += __shfl_down_sync(0xFFFFFFFFu, acc, off);
            if (lane == 0) g_part[u * 8 + wid] = acc;
        }
    }
}

// ---------------------------------------------------------------------------
// Final combine: fixed-order parallel reduction over the three slot ranges,
// then scalar combine + work counter reset.
// ---------------------------------------------------------------------------
__global__ void __launch_bounds__(512)
final_kernel(const float* __restrict__ beta_p, float* __restrict__ out)
{
    __shared__ float red[512];
    __shared__ float s_int, s_flt;
    const int tid = threadIdx.x;

    // integral slots [0, U_INT*8)
    float s = 0.0f;
    for (int i = tid; i < U_INT * 8; i += 512) s += g_part[i];
    red[tid] = s;
    __syncthreads();
    for (int st = 256; st > 0; st >>= 1) {
        if (tid < st) red[tid] += red[tid + st];
        __syncthreads();
    }
    if (tid == 0) s_int = red[0];
    __syncthreads();

    // flt slots [U_INT*8, (U_INT+U_FLT)*8)
    s = 0.0f;
    if (tid < U_FLT * 8) s = g_part[U_INT * 8 + tid];
    red[tid] = s;
    __syncthreads();
    for (int st = 256; st > 0; st >>= 1) {
        if (tid < st) red[tid] += red[tid + st];
        __syncthreads();
    }
    if (tid == 0) s_flt = red[0];
    __syncthreads();

    if (tid == 0) {
        float prior_raw = 0.0f;
        #pragma unroll
        for (int i = 0; i < 8; i++) prior_raw += g_part[(U_INT + U_FLT) * 8 + i];

        const float beta   = beta_p[0];
        const float prior  = 10.0f * prior_raw;              // PENALTY
        const float result = 2.0f * (prior - beta * 262144.0f - s_flt
                              + 2.5066282746310002f * expf(beta) * s_int);
        out[0] = result;
        g_unit_ctr = 0;   // reset work-stealing counter for the next call
    }
}

// ---------------------------------------------------------------------------
extern "C" void kernel_launch(void* const* d_in, const int* in_sizes, int n_in,
                              void* d_out, int out_size)
{
    const float* Z    = (const float*)d_in[0];
    const float* beta = (const float*)d_in[1];
    const float* ts   = (const float*)d_in[2];
    const int*   snd  = (const int*)d_in[3];
    const int*   rcv  = (const int*)d_in[4];
    const int*   nds  = (const int*)d_in[5];
    const int*   su   = (const int*)d_in[6];
    const float* cp   = (const float*)d_in[7];
    float* out = (float*)d_out;

    fused_kernel<<<GRID, 256>>>(Z, su, cp, ts, snd, rcv, nds);
    final_kernel<<<1, 512>>>(beta, out);
}

// round 10
// speedup vs baseline: 1.5386x; 1.0249x over previous
#include <cuda_runtime.h>
#include <math.h>

// Problem constants (fixed by the dataset)
#define N_NODES   8192
#define N_EDGES   262144
#define BS_NODES  4096
#define N_SEND    2048
#define ZSTRIDE   18         // 2 * (K+1)

#define IC        256        // senders staged per integral unit
#define U_FLT     64         // flt units, 4096 edges each (scheduled FIRST)
#define U_INT     2048       // 8 seg * 32 j-tiles * 8 i-chunks
#define U_ALL     (U_FLT + 1 + U_INT)   // flt, prior, integral
#define N_PARTS   (U_ALL * 8)           // one slot per (unit, warp)
#define GRID      592        // 4 * 148 SMs; dynamic stealing absorbs imbalance

__device__ float g_part[N_PARTS];
__device__ unsigned int g_unit_ctr = 0;

// ---------------------------------------------------------------------------
// Packed fp32 (f32x2) helpers
// ---------------------------------------------------------------------------
typedef unsigned long long u64_t;
union F2U { float2 f; u64_t u; };

__device__ __forceinline__ u64_t f2u(float2 v) { F2U x; x.f = v; return x.u; }
__device__ __forceinline__ float2 u2f(u64_t v) { F2U x; x.u = v; return x.f; }

__device__ __forceinline__ float2 fma2(float2 a, float2 b, float2 c) {
    u64_t d;
    asm("fma.rn.f32x2 %0, %1, %2, %3;"
        : "=l"(d) : "l"(f2u(a)), "l"(f2u(b)), "l"(f2u(c)));
    return u2f(d);
}
__device__ __forceinline__ float2 mul2(float2 a, float2 b) {
    u64_t d;
    asm("mul.rn.f32x2 %0, %1, %2;" : "=l"(d) : "l"(f2u(a)), "l"(f2u(b)));
    return u2f(d);
}
__device__ __forceinline__ float2 add2(float2 a, float2 b) {
    u64_t d;
    asm("add.rn.f32x2 %0, %1, %2;" : "=l"(d) : "l"(f2u(a)), "l"(f2u(b)));
    return u2f(d);
}
__device__ __forceinline__ float2 neg2(float2 a) {
    F2U x; x.f = a; x.u ^= 0x8000000080000000ULL; return x.f;
}
__device__ __forceinline__ float2 abs2(float2 a) {
    F2U x; x.f = a; x.u &= 0x7FFFFFFF7FFFFFFFULL; return x.f;
}
__device__ __forceinline__ float2 sub2(float2 a, float2 b) { return add2(a, neg2(b)); }
__device__ __forceinline__ float2 splat2(float v) { return make_float2(v, v); }
#define FZERO splat2(0.0f)

__device__ __forceinline__ float fast_rsqrt(float x) {
    float r; asm("rsqrt.approx.f32 %0, %1;" : "=f"(r) : "f"(x)); return r;
}
__device__ __forceinline__ float fast_ex2(float x) {
    float r; asm("ex2.approx.f32 %0, %1;" : "=f"(r) : "f"(x)); return r;
}

// log2(erfc(t)) + ea for t >= 0: degree-5 poly (njuffa-derived, log2(e)
// folded in; |erf err| <= ~1.3e-4 worst case), final op fused with the
// +ea add: returns poly(t)*t + ea.
__device__ __forceinline__ float2 log2_erfc_ea(float2 t, float2 ea) {
    const float2 D5 = splat2(-5.603370e-3f);
    const float2 D4 = splat2( 3.499207e-2f);
    const float2 D3 = splat2(-1.540479e-1f);
    const float2 D2 = splat2(-9.158902e-1f);
    const float2 D1 = splat2(-1.6283940f);
    float2 q = fma2(D5, t, D4);
    q = fma2(q, t, D3);
    q = fma2(q, t, D2);
    q = fma2(q, t, D1);
    return fma2(q, t, ea);
}

// ---------------------------------------------------------------------------
// Fused kernel: one dynamic work-stealing pool over
//   units [0, U_FLT):    flt, 4096 edges each  (memory-latency bound, FIRST
//                        so they overlap with compute-bound integral units)
//   unit  U_FLT:         prior
//   units [U_FLT+1, ..): integral (seg k, 256-j tile, 256-i chunk)
// Every unit writes per-(unit,warp) partials -> final fixed-order sum is
// bitwise deterministic regardless of which block ran which unit.
//
// Integral identities (w = Zs0-Zr0, v = DZs-DZr): D=|w|^2, S=|v|^2, C=-(v.w).
// Sv seeded with +1e-20 so the diagonal flows to exactly 0 with no mask
// (traced: Dv=+0 -> er=+0 -> ea=+0; q1,q2 ~ -1.6e-10,0 -> all exp2 == 1 ->
// terms == 0). e = S*mu^2 - D <= 0 by Cauchy-Schwarz (tiny +eps from fma
// rounding is harmless). erf applied as ex - exp2(ea + log2_erfc(|x|)) >= 0
// with the sign restored by a packed OR of the argument's sign bit.
// ---------------------------------------------------------------------------
__global__ void __launch_bounds__(256)
fused_kernel(const float* __restrict__ Z,
             const int*   __restrict__ su,
             const float* __restrict__ cp,
             const float* __restrict__ ts,
             const int*   __restrict__ snd,
             const int*   __restrict__ rcv,
             const int*   __restrict__ nodes)
{
    // float4-packed sender params: sP[i/2] = {a0[i],a0[i+1],a1[i],a1[i+1]},
    // sQ likewise for d0/d1 -> 2x LDS.128 per inner iteration.
    __shared__ __align__(16) float sP[IC * 2], sQ[IC * 2];
    __shared__ int s_unit;

    const int tid  = threadIdx.x;
    const int wid  = tid >> 5;
    const int lane = tid & 31;

    const float2 L2E  = splat2(1.4426950408889634f);
    const float2 TINY = splat2(1e-20f);
    const u64_t  SGN  = 0x8000000080000000ULL;

    for (;;) {
        __syncthreads();
        if (tid == 0) s_unit = (int)atomicAdd(&g_unit_ctr, 1u);
        __syncthreads();
        const int u = s_unit;
        if (u >= U_ALL) break;

        if (u >= U_FLT + 1) {
            // ---------------- integral unit ----------------
            const int ui  = u - (U_FLT + 1);
            const int k   = ui >> 8;        // 0..7
            const int rem = ui & 255;
            const int jt  = rem >> 3;       // 0..31
            const int ic  = rem & 7;        // 0..7

            const int j = jt * 256 + tid;
            const float* zr = Z + j * ZSTRIDE;
            const float r0  = zr[k];
            const float rn0 = zr[k + 1];
            const float r1  = zr[9 + k];
            const float rn1 = zr[9 + k + 1];
            const float2 R0  = splat2(r0);
            const float2 R1  = splat2(r1);
            const float2 DR0 = splat2(rn0 - r0);
            const float2 DR1 = splat2(rn1 - r1);

            {
                const int sidx = su[ic * IC + tid];
                const float* zs = Z + sidx * ZSTRIDE;
                const float a0 = zs[k];
                const float b0 = zs[k + 1];
                const float a1 = zs[9 + k];
                const float b1 = zs[9 + k + 1];
                const int base = 4 * (tid >> 1) + (tid & 1);
                sP[base]     = a0;
                sP[base + 2] = a1;
                sQ[base]     = b0 - a0;
                sQ[base + 2] = b1 - a1;
            }
            __syncthreads();

            float2 acc = FZERO;
            #pragma unroll 4
            for (int i = 0; i < IC / 2; i++) {
                const float4 P = *(const float4*)&sP[4 * i];
                const float4 Q = *(const float4*)&sQ[4 * i];
                const float2 A0  = make_float2(P.x, P.y);
                const float2 A1  = make_float2(P.z, P.w);
                const float2 Dz0 = make_float2(Q.x, Q.y);
                const float2 Dz1 = make_float2(Q.z, Q.w);

                const float2 w0 = sub2(A0, R0);
                const float2 w1 = sub2(A1, R1);
                const float2 v0 = sub2(Dz0, DR0);
                const float2 v1 = sub2(Dz1, DR1);

                const float2 Dv = fma2(w1, w1, mul2(w0, w0));
                const float2 Sv = fma2(v1, v1, fma2(v0, v0, TINY));
                const float2 nC = fma2(v1, w1, mul2(v0, w0));

                float2 irs;
                irs.x = fast_rsqrt(Sv.x);
                irs.y = fast_rsqrt(Sv.y);

                const float2 ncir = mul2(nC, irs);           // -mu*sqrt(S)
                const float2 x1   = fma2(Sv, irs, ncir);     // (1-mu)*sqrt(S)

                // ea = (ncir^2 - D)*l2e  (<= 0 up to rounding)
                const float2 er = fma2(ncir, ncir, neg2(Dv));
                const float2 ea = mul2(er, L2E);

                const float2 q1 = log2_erfc_ea(abs2(x1),   ea);
                const float2 q2 = log2_erfc_ea(abs2(ncir), ea);

                float2 ex, G1, G2;
                ex.x = fast_ex2(ea.x);  ex.y = fast_ex2(ea.y);
                G1.x = fast_ex2(q1.x);  G1.y = fast_ex2(q1.y);
                G2.x = fast_ex2(q2.x);  G2.y = fast_ex2(q2.y);

                // term = ex*erf(|.|) >= 0; apply sign via packed OR
                const float2 t1 = sub2(ex, G1);
                const float2 t2 = sub2(ex, G2);
                const float2 u1 = u2f(f2u(t1) | (f2u(x1)   & SGN));
                const float2 v2 = u2f(f2u(t2) | (f2u(ncir) & SGN));

                // ex*(erf(x1) + erf(cir)) = u1 - v2
                const float2 es = sub2(u1, v2);
                acc = fma2(es, irs, acc);
            }

            const float dt = cp[k + 1] - cp[k];
            // fold sigma's 1/sqrt(2), the cdf 0.5 and the scan 0.5
            float tot = (acc.x + acc.y) * (dt * 0.17677669529663687f);
            #pragma unroll
            for (int off = 16; off > 0; off >>= 1)
                tot += __shfl_down_sync(0xFFFFFFFFu, tot, off);
            if (lane == 0) g_part[u * 8 + wid] = tot;

        } else if (u < U_FLT) {
            // ---------------- flt unit (4096 edges) ----------------
            const int base = u * 4096;
            const float seg = cp[1] - cp[0];

            float acc = 0.0f;
            #pragma unroll 4
            for (int r = 0; r < 16; r++) {
                const int e = base + r * 256 + tid;
                const float t  = ts[e];
                const float q  = t / seg;
                const float kf = floorf(q);
                const int   ka = (int)kf;
                const float d  = q - kf;
                const float od = 1.0f - d;

                const float* zs = Z + snd[e] * ZSTRIDE;
                const float* zr = Z + rcv[e] * ZSTRIDE;
                const float sc0 = zs[ka],     sn0 = zs[ka + 1];
                const float sc1 = zs[9 + ka], sn1 = zs[9 + ka + 1];
                const float rc0 = zr[ka],     rn0 = zr[ka + 1];
                const float rc1 = zr[9 + ka], rn1 = zr[9 + ka + 1];

                const float scrc = sc0 * rc0 + sc1 * rc1;
                const float scsc = sc0 * sc0 + sc1 * sc1;
                const float rcrc = rc0 * rc0 + rc1 * rc1;
                const float scrn = sc0 * rn0 + sc1 * rn1;
                const float snrc = sn0 * rc0 + sn1 * rc1;
                const float scsn = sc0 * sn0 + sc1 * sn1;
                const float rcrn = rc0 * rn0 + rc1 * rn1;
                const float snrn = sn0 * rn0 + sn1 * rn1;
                const float snsn = sn0 * sn0 + sn1 * sn1;
                const float rnrn = rn0 * rn0 + rn1 * rn1;

                acc += od * od * (2.0f * scrc - scsc - rcrc)
                     + 2.0f * d * od * (scrn + snrc - scsn - rcrn)
                     + d * d * (2.0f * snrn - snsn - rnrn);
            }
            #pragma unroll
            for (int off = 16; off > 0; off >>= 1)
                acc += __shfl_down_sync(0xFFFFFFFFu, acc, off);
            if (lane == 0) g_part[u * 8 + wid] = acc;

        } else {
            // ---------------- prior unit (4096 nodes) ----------------
            float acc = 0.0f;
            #pragma unroll
            for (int r = 0; r < 16; r++) {
                const int n = nodes[r * 256 + tid];
                const float* z = Z + n * ZSTRIDE;
                #pragma unroll
                for (int dim = 0; dim < 2; dim++) {
                    const float* zd = z + dim * 9;
                    float prev = zd[0];
                    acc += prev * prev;
                    #pragma unroll
                    for (int kk = 1; kk <= 8; kk++) {
                        const float cur = zd[kk];
                        const float df  = cur - prev;
                        acc += df * df;
                        prev = cur;
                    }
                }
            }
            #pragma unroll
            for (int off = 16; off > 0; off >>= 1)
                acc += __shfl_down_sync(0xFFFFFFFFu, acc, off);
            if (lane == 0) g_part[u * 8 + wid] = acc;
        }
    }
}

// ---------------------------------------------------------------------------
// Final combine: fixed-order parallel reduction over the three slot ranges,
// then scalar combine + work counter reset.
// ---------------------------------------------------------------------------
__global__ void __launch_bounds__(512)
final_kernel(const float* __restrict__ beta_p, float* __restrict__ out)
{
    __shared__ float red[512];
    __shared__ float s_int, s_flt;
    const int tid = threadIdx.x;

    // integral slots [(U_FLT+1)*8, U_ALL*8)
    float s = 0.0f;
    for (int i = tid; i < U_INT * 8; i += 512) s += g_part[(U_FLT + 1) * 8 + i];
    red[tid] = s;
    __syncthreads();
    for (int st = 256; st > 0; st >>= 1) {
        if (tid < st) red[tid] += red[tid + st];
        __syncthreads();
    }
    if (tid == 0) s_int = red[0];
    __syncthreads();

    // flt slots [0, U_FLT*8)
    s = 0.0f;
    if (tid < U_FLT * 8) s = g_part[tid];
    red[tid] = s;
    __syncthreads();
    for (int st = 256; st > 0; st >>= 1) {
        if (tid < st) red[tid] += red[tid + st];
        __syncthreads();
    }
    if (tid == 0) s_flt = red[0];
    __syncthreads();

    if (tid == 0) {
        float prior_raw = 0.0f;
        #pragma unroll
        for (int i = 0; i < 8; i++) prior_raw += g_part[U_FLT * 8 + i];

        const float beta   = beta_p[0];
        const float prior  = 10.0f * prior_raw;              // PENALTY
        const float result = 2.0f * (prior - beta * 262144.0f - s_flt
                              + 2.5066282746310002f * expf(beta) * s_int);
        out[0] = result;
        g_unit_ctr = 0;   // reset work-stealing counter for the next call
    }
}

// ---------------------------------------------------------------------------
extern "C" void kernel_launch(void* const* d_in, const int* in_sizes, int n_in,
                              void* d_out, int out_size)
{
    const float* Z    = (const float*)d_in[0];
    const float* beta = (const float*)d_in[1];
    const float* ts   = (const float*)d_in[2];
    const int*   snd  = (const int*)d_in[3];
    const int*   rcv  = (const int*)d_in[4];
    const int*   nds  = (const int*)d_in[5];
    const int*   su   = (const int*)d_in[6];
    const float* cp   = (const float*)d_in[7];
    float* out = (float*)d_out;

    fused_kernel<<<GRID, 256>>>(Z, su, cp, ts, snd, rcv, nds);
    final_kernel<<<1, 512>>>(beta, out);
}

// round 11
// speedup vs baseline: 1.5546x; 1.0104x over previous
#include <cuda_runtime.h>
#include <math.h>

// Problem constants (fixed by the dataset)
#define N_NODES   8192
#define N_EDGES   262144
#define BS_NODES  4096
#define N_SEND    2048
#define N_NOTS    (N_NODES - N_SEND)    // 6144
#define ZSTRIDE   18                    // 2 * (K+1)

#define IC        256        // senders staged per integral unit
#define U_FLT     64         // flt units, 4096 edges each (scheduled FIRST)
#define U_A       1536       // 8 seg * 24 notS-j-tiles * 8 i-chunks
#define U_B       288        // 8 seg * 36 (a<=b) S-tile pairs
#define U_ALL     (U_FLT + 1 + U_A + U_B)
#define N_PARTS   (U_ALL * 8)           // one slot per (unit, warp)
#define GRID      592        // 4 * 148 SMs; dynamic stealing absorbs imbalance

__device__ float g_part[N_PARTS];
__device__ int   g_notS[N_NOTS];
__device__ unsigned int g_unit_ctr = 0;

// triangle tile-pair table: (a, b) with a <= b, 36 entries
__device__ const signed char TA[36] =
    {0,0,0,0,0,0,0,0, 1,1,1,1,1,1,1, 2,2,2,2,2,2, 3,3,3,3,3, 4,4,4,4, 5,5,5, 6,6, 7};
__device__ const signed char TB[36] =
    {0,1,2,3,4,5,6,7, 1,2,3,4,5,6,7, 2,3,4,5,6,7, 3,4,5,6,7, 4,5,6,7, 5,6,7, 6,7, 7};

// ---------------------------------------------------------------------------
// Packed fp32 (f32x2) helpers
// ---------------------------------------------------------------------------
typedef unsigned long long u64_t;
union F2U { float2 f; u64_t u; };

__device__ __forceinline__ u64_t f2u(float2 v) { F2U x; x.f = v; return x.u; }
__device__ __forceinline__ float2 u2f(u64_t v) { F2U x; x.u = v; return x.f; }

__device__ __forceinline__ float2 fma2(float2 a, float2 b, float2 c) {
    u64_t d;
    asm("fma.rn.f32x2 %0, %1, %2, %3;"
        : "=l"(d) : "l"(f2u(a)), "l"(f2u(b)), "l"(f2u(c)));
    return u2f(d);
}
__device__ __forceinline__ float2 mul2(float2 a, float2 b) {
    u64_t d;
    asm("mul.rn.f32x2 %0, %1, %2;" : "=l"(d) : "l"(f2u(a)), "l"(f2u(b)));
    return u2f(d);
}
__device__ __forceinline__ float2 add2(float2 a, float2 b) {
    u64_t d;
    asm("add.rn.f32x2 %0, %1, %2;" : "=l"(d) : "l"(f2u(a)), "l"(f2u(b)));
    return u2f(d);
}
__device__ __forceinline__ float2 neg2(float2 a) {
    F2U x; x.f = a; x.u ^= 0x8000000080000000ULL; return x.f;
}
__device__ __forceinline__ float2 abs2(float2 a) {
    F2U x; x.f = a; x.u &= 0x7FFFFFFF7FFFFFFFULL; return x.f;
}
__device__ __forceinline__ float2 sub2(float2 a, float2 b) { return add2(a, neg2(b)); }
__device__ __forceinline__ float2 splat2(float v) { return make_float2(v, v); }
#define FZERO splat2(0.0f)

__device__ __forceinline__ float fast_rsqrt(float x) {
    float r; asm("rsqrt.approx.f32 %0, %1;" : "=f"(r) : "f"(x)); return r;
}
__device__ __forceinline__ float fast_ex2(float x) {
    float r; asm("ex2.approx.f32 %0, %1;" : "=f"(r) : "f"(x)); return r;
}

// log2(erfc(t)) + ea for t >= 0: degree-5 poly (njuffa-derived, log2(e)
// folded in; |erf err| <= ~1.3e-4 worst case), final op fused with +ea.
__device__ __forceinline__ float2 log2_erfc_ea(float2 t, float2 ea) {
    const float2 D5 = splat2(-5.603370e-3f);
    const float2 D4 = splat2( 3.499207e-2f);
    const float2 D3 = splat2(-1.540479e-1f);
    const float2 D2 = splat2(-9.158902e-1f);
    const float2 D1 = splat2(-1.6283940f);
    float2 q = fma2(D5, t, D4);
    q = fma2(q, t, D3);
    q = fma2(q, t, D2);
    q = fma2(q, t, D1);
    return fma2(q, t, ea);
}

// ---------------------------------------------------------------------------
// prep kernel: deterministic compaction of non-senders via rank.
// For node n: rank = #(su <= n) (binary search). If n not in su:
// g_notS[n - rank] = n. No atomics -> fully deterministic.
// ---------------------------------------------------------------------------
__global__ void __launch_bounds__(256)
prep_kernel(const int* __restrict__ su)
{
    const int n = blockIdx.x * 256 + threadIdx.x;   // grid 32 x 256 = 8192
    int lo = 0, hi = N_SEND;
    while (lo < hi) {
        const int mid = (lo + hi) >> 1;
        if (su[mid] <= n) lo = mid + 1; else hi = mid;
    }
    const bool member = (lo > 0) && (su[lo - 1] == n);
    if (!member) g_notS[n - lo] = n;
}

// ---------------------------------------------------------------------------
// Fused kernel: one dynamic work-stealing pool over
//   [0, U_FLT):  flt units (memory-latency bound, first to overlap compute)
//   U_FLT:       prior unit
//   A units:     integral, i in S (2048) x j in notS (6144)
//   B units:     integral, S x S triangle tiles; off-diag tiles scaled x2
//                (f(i,j) == f(j,i) bit-exactly: w->-w, v->-v leave
//                 D=|w|^2, S=|v|^2, v.w invariant)
// Per-(unit,warp) partial slots -> fixed-order final sum is deterministic.
//
// Integral math identical to R10 (verified): w = Zs0-Zr0, v = DZs-DZr,
// D=|w|^2, S=|v|^2(+1e-20 seed), C=-(v.w); diagonal flows to exactly 0;
// erf via ex - exp2(ea + log2_erfc(|x|)), sign restored by packed OR.
// ---------------------------------------------------------------------------
__global__ void __launch_bounds__(256)
fused_kernel(const float* __restrict__ Z,
             const int*   __restrict__ su,
             const float* __restrict__ cp,
             const float* __restrict__ ts,
             const int*   __restrict__ snd,
             const int*   __restrict__ rcv,
             const int*   __restrict__ nodes)
{
    // float4-packed sender params
    __shared__ __align__(16) float sP[IC * 2], sQ[IC * 2];
    __shared__ int s_unit[2];

    const int tid  = threadIdx.x;
    const int wid  = tid >> 5;
    const int lane = tid & 31;

    const float2 L2E  = splat2(1.4426950408889634f);
    const float2 TINY = splat2(1e-20f);
    const u64_t  SGN  = 0x8000000080000000ULL;

    for (int it = 0; ; it++) {
        const int p = it & 1;
        if (tid == 0) s_unit[p] = (int)atomicAdd(&g_unit_ctr, 1u);
        __syncthreads();            // publishes s_unit[p]; also guards sP/sQ
        const int u = s_unit[p];
        if (u >= U_ALL) break;

        if (u >= U_FLT + 1) {
            // ---------------- integral unit (A or B) ----------------
            const int ui = u - (U_FLT + 1);
            int k, jnode, ichunk;
            float factor;
            if (ui < U_A) {
                k = ui / (24 * 8);
                const int rem = ui % (24 * 8);
                const int jt  = rem >> 3;          // 0..23
                ichunk = rem & 7;
                jnode  = g_notS[jt * 256 + tid];
                factor = 1.0f;
            } else {
                const int ub = ui - U_A;
                k = ub / 36;
                const int tp = ub % 36;
                const int a = TA[tp], b = TB[tp];
                ichunk = a;
                jnode  = su[b * 256 + tid];
                factor = (a == b) ? 1.0f : 2.0f;
            }

            const float* zr = Z + jnode * ZSTRIDE;
            const float r0  = zr[k];
            const float rn0 = zr[k + 1];
            const float r1  = zr[9 + k];
            const float rn1 = zr[9 + k + 1];
            const float2 R0  = splat2(r0);
            const float2 R1  = splat2(r1);
            const float2 DR0 = splat2(rn0 - r0);
            const float2 DR1 = splat2(rn1 - r1);

            {
                const int sidx = su[ichunk * IC + tid];
                const float* zs = Z + sidx * ZSTRIDE;
                const float a0 = zs[k];
                const float b0 = zs[k + 1];
                const float a1 = zs[9 + k];
                const float b1 = zs[9 + k + 1];
                const int base = 4 * (tid >> 1) + (tid & 1);
                sP[base]     = a0;
                sP[base + 2] = a1;
                sQ[base]     = b0 - a0;
                sQ[base + 2] = b1 - a1;
            }
            __syncthreads();

            float2 acc = FZERO;
            #pragma unroll 4
            for (int i = 0; i < IC / 2; i++) {
                const float4 P = *(const float4*)&sP[4 * i];
                const float4 Q = *(const float4*)&sQ[4 * i];
                const float2 A0  = make_float2(P.x, P.y);
                const float2 A1  = make_float2(P.z, P.w);
                const float2 Dz0 = make_float2(Q.x, Q.y);
                const float2 Dz1 = make_float2(Q.z, Q.w);

                const float2 w0 = sub2(A0, R0);
                const float2 w1 = sub2(A1, R1);
                const float2 v0 = sub2(Dz0, DR0);
                const float2 v1 = sub2(Dz1, DR1);

                const float2 Dv = fma2(w1, w1, mul2(w0, w0));
                const float2 Sv = fma2(v1, v1, fma2(v0, v0, TINY));
                const float2 nC = fma2(v1, w1, mul2(v0, w0));

                float2 irs;
                irs.x = fast_rsqrt(Sv.x);
                irs.y = fast_rsqrt(Sv.y);

                const float2 ncir = mul2(nC, irs);           // -mu*sqrt(S)
                const float2 x1   = fma2(Sv, irs, ncir);     // (1-mu)*sqrt(S)

                const float2 er = fma2(ncir, ncir, neg2(Dv));
                const float2 ea = mul2(er, L2E);

                const float2 q1 = log2_erfc_ea(abs2(x1),   ea);
                const float2 q2 = log2_erfc_ea(abs2(ncir), ea);

                float2 ex, G1, G2;
                ex.x = fast_ex2(ea.x);  ex.y = fast_ex2(ea.y);
                G1.x = fast_ex2(q1.x);  G1.y = fast_ex2(q1.y);
                G2.x = fast_ex2(q2.x);  G2.y = fast_ex2(q2.y);

                const float2 t1 = sub2(ex, G1);
                const float2 t2 = sub2(ex, G2);
                const float2 u1 = u2f(f2u(t1) | (f2u(x1)   & SGN));
                const float2 v2 = u2f(f2u(t2) | (f2u(ncir) & SGN));

                const float2 es = sub2(u1, v2);
                acc = fma2(es, irs, acc);
            }

            const float dt = cp[k + 1] - cp[k];
            // fold sigma's 1/sqrt(2), cdf 0.5, scan 0.5, and triangle factor
            float tot = (acc.x + acc.y) * (dt * factor * 0.17677669529663687f);
            #pragma unroll
            for (int off = 16; off > 0; off >>= 1)
                tot += __shfl_down_sync(0xFFFFFFFFu, tot, off);
            if (lane == 0) g_part[u * 8 + wid] = tot;

        } else if (u < U_FLT) {
            // ---------------- flt unit (4096 edges) ----------------
            const int base = u * 4096;
            const float seg = cp[1] - cp[0];

            float acc = 0.0f;
            #pragma unroll 4
            for (int r = 0; r < 16; r++) {
                const int e = base + r * 256 + tid;
                const float t  = ts[e];
                const float q  = t / seg;
                const float kf = floorf(q);
                const int   ka = (int)kf;
                const float d  = q - kf;
                const float od = 1.0f - d;

                const float* zs = Z + snd[e] * ZSTRIDE;
                const float* zr = Z + rcv[e] * ZSTRIDE;
                const float sc0 = zs[ka],     sn0 = zs[ka + 1];
                const float sc1 = zs[9 + ka], sn1 = zs[9 + ka + 1];
                const float rc0 = zr[ka],     rn0 = zr[ka + 1];
                const float rc1 = zr[9 + ka], rn1 = zr[9 + ka + 1];

                const float scrc = sc0 * rc0 + sc1 * rc1;
                const float scsc = sc0 * sc0 + sc1 * sc1;
                const float rcrc = rc0 * rc0 + rc1 * rc1;
                const float scrn = sc0 * rn0 + sc1 * rn1;
                const float snrc = sn0 * rc0 + sn1 * rc1;
                const float scsn = sc0 * sn0 + sc1 * sn1;
                const float rcrn = rc0 * rn0 + rc1 * rn1;
                const float snrn = sn0 * rn0 + sn1 * rn1;
                const float snsn = sn0 * sn0 + sn1 * sn1;
                const float rnrn = rn0 * rn0 + rn1 * rn1;

                acc += od * od * (2.0f * scrc - scsc - rcrc)
                     + 2.0f * d * od * (scrn + snrc - scsn - rcrn)
                     + d * d * (2.0f * snrn - snsn - rnrn);
            }
            #pragma unroll
            for (int off = 16; off > 0; off >>= 1)
                acc += __shfl_down_sync(0xFFFFFFFFu, acc, off);
            if (lane == 0) g_part[u * 8 + wid] = acc;

        } else {
            // ---------------- prior unit (4096 nodes) ----------------
            float acc = 0.0f;
            #pragma unroll
            for (int r = 0; r < 16; r++) {
                const int n = nodes[r * 256 + tid];
                const float* z = Z + n * ZSTRIDE;
                #pragma unroll
                for (int dim = 0; dim < 2; dim++) {
                    const float* zd = z + dim * 9;
                    float prev = zd[0];
                    acc += prev * prev;
                    #pragma unroll
                    for (int kk = 1; kk <= 8; kk++) {
                        const float cur = zd[kk];
                        const float df  = cur - prev;
                        acc += df * df;
                        prev = cur;
                    }
                }
            }
            #pragma unroll
            for (int off = 16; off > 0; off >>= 1)
                acc += __shfl_down_sync(0xFFFFFFFFu, acc, off);
            if (lane == 0) g_part[u * 8 + wid] = acc;
        }
    }
}

// ---------------------------------------------------------------------------
// Final combine: fixed-order parallel reduction over the slot ranges,
// then scalar combine + work counter reset.
// ---------------------------------------------------------------------------
__global__ void __launch_bounds__(512)
final_kernel(const float* __restrict__ beta_p, float* __restrict__ out)
{
    __shared__ float red[512];
    __shared__ float s_int, s_flt;
    const int tid = threadIdx.x;

    // integral slots [(U_FLT+1)*8, U_ALL*8)
    float s = 0.0f;
    for (int i = tid; i < (U_A + U_B) * 8; i += 512)
        s += g_part[(U_FLT + 1) * 8 + i];
    red[tid] = s;
    __syncthreads();
    for (int st = 256; st > 0; st >>= 1) {
        if (tid < st) red[tid] += red[tid + st];
        __syncthreads();
    }
    if (tid == 0) s_int = red[0];
    __syncthreads();

    // flt slots [0, U_FLT*8)
    s = 0.0f;
    if (tid < U_FLT * 8) s = g_part[tid];
    red[tid] = s;
    __syncthreads();
    for (int st = 256; st > 0; st >>= 1) {
        if (tid < st) red[tid] += red[tid + st];
        __syncthreads();
    }
    if (tid == 0) s_flt = red[0];
    __syncthreads();

    if (tid == 0) {
        float prior_raw = 0.0f;
        #pragma unroll
        for (int i = 0; i < 8; i++) prior_raw += g_part[U_FLT * 8 + i];

        const float beta   = beta_p[0];
        const float prior  = 10.0f * prior_raw;              // PENALTY
        const float result = 2.0f * (prior - beta * 262144.0f - s_flt
                              + 2.5066282746310002f * expf(beta) * s_int);
        out[0] = result;
        g_unit_ctr = 0;   // reset work-stealing counter for the next call
    }
}

// ---------------------------------------------------------------------------
extern "C" void kernel_launch(void* const* d_in, const int* in_sizes, int n_in,
                              void* d_out, int out_size)
{
    const float* Z    = (const float*)d_in[0];
    const float* beta = (const float*)d_in[1];
    const float* ts   = (const float*)d_in[2];
    const int*   snd  = (const int*)d_in[3];
    const int*   rcv  = (const int*)d_in[4];
    const int*   nds  = (const int*)d_in[5];
    const int*   su   = (const int*)d_in[6];
    const float* cp   = (const float*)d_in[7];
    float* out = (float*)d_out;

    prep_kernel<<<N_NODES / 256, 256>>>(su);
    fused_kernel<<<GRID, 256>>>(Z, su, cp, ts, snd, rcv, nds);
    final_kernel<<<1, 512>>>(beta, out);
}

// round 12
// speedup vs baseline: 1.5777x; 1.0148x over previous
#include <cuda_runtime.h>
#include <math.h>

// Problem constants (fixed by the dataset)
#define N_NODES   8192
#define N_EDGES   262144
#define BS_NODES  4096
#define N_SEND    2048
#define N_NOTS    (N_NODES - N_SEND)    // 6144
#define ZSTRIDE   18                    // 2 * (K+1)

// Unit pool layout (grab order = listed order; big units before small: LPT)
#define U_PREP    8                     // build g_notS, 1024 nodes each
#define B_PRIOR   (U_PREP)              // 1 prior unit
#define B_FLT     (B_PRIOR + 1)
#define U_FLT     64                    // 4096 edges each
#define B_B       (B_FLT + U_FLT)       // 73
#define U_B       288                   // 8 seg * 36 triangle tile-pairs (256x256)
#define B_A       (B_B + U_B)           // 361
#define U_A       3072                  // 8 seg * 24 j-tiles * 16 i-chunks (256x128)
#define U_ALL     (B_A + U_A)           // 3433
#define N_PARTS   (U_ALL * 8)
#define GRID      592                   // 4 * 148 SMs (all co-resident)

__device__ float g_part[N_PARTS];
__device__ int   g_notS[N_NOTS];
__device__ unsigned int g_unit_ctr = 0;
__device__ unsigned int g_prep_flag = 0;

// triangle tile-pair table: (a, b) with a <= b, 36 entries
__device__ const signed char TA[36] =
    {0,0,0,0,0,0,0,0, 1,1,1,1,1,1,1, 2,2,2,2,2,2, 3,3,3,3,3, 4,4,4,4, 5,5,5, 6,6, 7};
__device__ const signed char TB[36] =
    {0,1,2,3,4,5,6,7, 1,2,3,4,5,6,7, 2,3,4,5,6,7, 3,4,5,6,7, 4,5,6,7, 5,6,7, 6,7, 7};

// ---------------------------------------------------------------------------
// Packed fp32 (f32x2) helpers
// ---------------------------------------------------------------------------
typedef unsigned long long u64_t;
union F2U { float2 f; u64_t u; };

__device__ __forceinline__ u64_t f2u(float2 v) { F2U x; x.f = v; return x.u; }
__device__ __forceinline__ float2 u2f(u64_t v) { F2U x; x.u = v; return x.f; }

__device__ __forceinline__ float2 fma2(float2 a, float2 b, float2 c) {
    u64_t d;
    asm("fma.rn.f32x2 %0, %1, %2, %3;"
        : "=l"(d) : "l"(f2u(a)), "l"(f2u(b)), "l"(f2u(c)));
    return u2f(d);
}
__device__ __forceinline__ float2 mul2(float2 a, float2 b) {
    u64_t d;
    asm("mul.rn.f32x2 %0, %1, %2;" : "=l"(d) : "l"(f2u(a)), "l"(f2u(b)));
    return u2f(d);
}
__device__ __forceinline__ float2 add2(float2 a, float2 b) {
    u64_t d;
    asm("add.rn.f32x2 %0, %1, %2;" : "=l"(d) : "l"(f2u(a)), "l"(f2u(b)));
    return u2f(d);
}
__device__ __forceinline__ float2 neg2(float2 a) {
    F2U x; x.f = a; x.u ^= 0x8000000080000000ULL; return x.f;
}
__device__ __forceinline__ float2 abs2(float2 a) {
    F2U x; x.f = a; x.u &= 0x7FFFFFFF7FFFFFFFULL; return x.f;
}
__device__ __forceinline__ float2 sub2(float2 a, float2 b) { return add2(a, neg2(b)); }
__device__ __forceinline__ float2 splat2(float v) { return make_float2(v, v); }
#define FZERO splat2(0.0f)

__device__ __forceinline__ float fast_rsqrt(float x) {
    float r; asm("rsqrt.approx.f32 %0, %1;" : "=f"(r) : "f"(x)); return r;
}
__device__ __forceinline__ float fast_ex2(float x) {
    float r; asm("ex2.approx.f32 %0, %1;" : "=f"(r) : "f"(x)); return r;
}

// log2(erfc(t)) + ea for t >= 0 (njuffa-derived deg-5, log2(e) folded;
// |erf err| <= ~1.3e-4 worst case), final op fused with +ea.
__device__ __forceinline__ float2 log2_erfc_ea(float2 t, float2 ea) {
    const float2 D5 = splat2(-5.603370e-3f);
    const float2 D4 = splat2( 3.499207e-2f);
    const float2 D3 = splat2(-1.540479e-1f);
    const float2 D2 = splat2(-9.158902e-1f);
    const float2 D1 = splat2(-1.6283940f);
    float2 q = fma2(D5, t, D4);
    q = fma2(q, t, D3);
    q = fma2(q, t, D2);
    q = fma2(q, t, D1);
    return fma2(q, t, ea);
}

// Shared integral inner loop over ITERS f32x2 sender pairs.
// Math identical to the R10/R11-verified chain: w = Zs0-Zr0, v = DZs-DZr,
// D=|w|^2, S=|v|^2(+1e-20 seed), C=-(v.w); diagonal flows to exactly 0;
// erf via ex - exp2(ea + log2_erfc(|x|)), sign restored by packed OR.
template <int ITERS>
__device__ __forceinline__ float2 integral_body(
    const float* sP, const float* sQ,
    float2 R0, float2 R1, float2 DR0, float2 DR1)
{
    const float2 L2E  = splat2(1.4426950408889634f);
    const float2 TINY = splat2(1e-20f);
    const u64_t  SGN  = 0x8000000080000000ULL;

    float2 acc = FZERO;
    #pragma unroll 4
    for (int i = 0; i < ITERS; i++) {
        const float4 P = *(const float4*)&sP[4 * i];
        const float4 Q = *(const float4*)&sQ[4 * i];
        const float2 A0  = make_float2(P.x, P.y);
        const float2 A1  = make_float2(P.z, P.w);
        const float2 Dz0 = make_float2(Q.x, Q.y);
        const float2 Dz1 = make_float2(Q.z, Q.w);

        const float2 w0 = sub2(A0, R0);
        const float2 w1 = sub2(A1, R1);
        const float2 v0 = sub2(Dz0, DR0);
        const float2 v1 = sub2(Dz1, DR1);

        const float2 Dv = fma2(w1, w1, mul2(w0, w0));
        const float2 Sv = fma2(v1, v1, fma2(v0, v0, TINY));
        const float2 nC = fma2(v1, w1, mul2(v0, w0));

        float2 irs;
        irs.x = fast_rsqrt(Sv.x);
        irs.y = fast_rsqrt(Sv.y);

        const float2 ncir = mul2(nC, irs);           // -mu*sqrt(S)
        const float2 x1   = fma2(Sv, irs, ncir);     // (1-mu)*sqrt(S)

        const float2 er = fma2(ncir, ncir, neg2(Dv));
        const float2 ea = mul2(er, L2E);

        const float2 q1 = log2_erfc_ea(abs2(x1),   ea);
        const float2 q2 = log2_erfc_ea(abs2(ncir), ea);

        float2 ex, G1, G2;
        ex.x = fast_ex2(ea.x);  ex.y = fast_ex2(ea.y);
        G1.x = fast_ex2(q1.x);  G1.y = fast_ex2(q1.y);
        G2.x = fast_ex2(q2.x);  G2.y = fast_ex2(q2.y);

        const float2 t1 = sub2(ex, G1);
        const float2 t2 = sub2(ex, G2);
        const float2 u1 = u2f(f2u(t1) | (f2u(x1)   & SGN));
        const float2 v2 = u2f(f2u(t2) | (f2u(ncir) & SGN));

        const float2 es = sub2(u1, v2);
        acc = fma2(es, irs, acc);
    }
    return acc;
}

// ---------------------------------------------------------------------------
// Fused kernel: one dynamic work-stealing pool:
//   [0, 8):       prep units (rank-compaction of non-senders; flag when done)
//   8:            prior unit
//   [9, 73):      flt units (memory-latency bound, early to overlap compute)
//   [73, 361):    B integral units: S x S triangle, 256x256 tiles, off-diag
//                 x2 (f(i,j)==f(j,i) bit-exactly)
//   [361, 3433):  A integral units: S-chunk(128) x notS-tile(256); A units
//                 spin on the prep flag before reading g_notS (all GRID
//                 blocks are co-resident -> prep always completes).
// Per-(unit,warp) partial slots -> fixed-order final sum is deterministic.
// ---------------------------------------------------------------------------
__global__ void __launch_bounds__(256)
fused_kernel(const float* __restrict__ Z,
             const int*   __restrict__ su,
             const float* __restrict__ cp,
             const float* __restrict__ ts,
             const int*   __restrict__ snd,
             const int*   __restrict__ rcv,
             const int*   __restrict__ nodes)
{
    __shared__ __align__(16) float sP[512], sQ[512];
    __shared__ int s_unit[2];

    const int tid  = threadIdx.x;
    const int wid  = tid >> 5;
    const int lane = tid & 31;

    for (int it = 0; ; it++) {
        const int p = it & 1;
        if (tid == 0) s_unit[p] = (int)atomicAdd(&g_unit_ctr, 1u);
        __syncthreads();            // publishes s_unit[p]; also guards sP/sQ
        const int u = s_unit[p];
        if (u >= U_ALL) break;

        if (u >= B_A) {
            // ---------------- A unit: S(128) x notS(256) ----------------
            const int ui  = u - B_A;
            const int k   = ui / 384;          // 0..7
            const int rem = ui % 384;
            const int jt  = rem >> 4;          // 0..23
            const int ic  = rem & 15;          // 0..15

            // wait for prep (first A grabs may race the prep units)
            if (tid == 0) {
                while (atomicAdd(&g_prep_flag, 0u) < U_PREP) {}
            }
            __syncthreads();

            const int jnode = g_notS[jt * 256 + tid];
            const float* zr = Z + jnode * ZSTRIDE;
            const float r0  = zr[k];
            const float rn0 = zr[k + 1];
            const float r1  = zr[9 + k];
            const float rn1 = zr[9 + k + 1];
            const float2 R0  = splat2(r0);
            const float2 R1  = splat2(r1);
            const float2 DR0 = splat2(rn0 - r0);
            const float2 DR1 = splat2(rn1 - r1);

            if (tid < 128) {
                const int sidx = su[ic * 128 + tid];
                const float* zs = Z + sidx * ZSTRIDE;
                const float a0 = zs[k];
                const float b0 = zs[k + 1];
                const float a1 = zs[9 + k];
                const float b1 = zs[9 + k + 1];
                const int base = 4 * (tid >> 1) + (tid & 1);
                sP[base]     = a0;
                sP[base + 2] = a1;
                sQ[base]     = b0 - a0;
                sQ[base + 2] = b1 - a1;
            }
            __syncthreads();

            const float2 acc = integral_body<64>(sP, sQ, R0, R1, DR0, DR1);

            const float dt = cp[k + 1] - cp[k];
            float tot = (acc.x + acc.y) * (dt * 0.17677669529663687f);
            #pragma unroll
            for (int off = 16; off > 0; off >>= 1)
                tot += __shfl_down_sync(0xFFFFFFFFu, tot, off);
            if (lane == 0) g_part[u * 8 + wid] = tot;

        } else if (u >= B_B) {
            // ---------------- B unit: S x S triangle tile (256x256) -------
            const int ub = u - B_B;
            const int k  = ub / 36;
            const int tp = ub % 36;
            const int a = TA[tp], b = TB[tp];
            const float factor = (a == b) ? 1.0f : 2.0f;

            const int jnode = su[b * 256 + tid];
            const float* zr = Z + jnode * ZSTRIDE;
            const float r0  = zr[k];
            const float rn0 = zr[k + 1];
            const float r1  = zr[9 + k];
            const float rn1 = zr[9 + k + 1];
            const float2 R0  = splat2(r0);
            const float2 R1  = splat2(r1);
            const float2 DR0 = splat2(rn0 - r0);
            const float2 DR1 = splat2(rn1 - r1);

            {
                const int sidx = su[a * 256 + tid];
                const float* zs = Z + sidx * ZSTRIDE;
                const float a0 = zs[k];
                const float b0 = zs[k + 1];
                const float a1 = zs[9 + k];
                const float b1 = zs[9 + k + 1];
                const int base = 4 * (tid >> 1) + (tid & 1);
                sP[base]     = a0;
                sP[base + 2] = a1;
                sQ[base]     = b0 - a0;
                sQ[base + 2] = b1 - a1;
            }
            __syncthreads();

            const float2 acc = integral_body<128>(sP, sQ, R0, R1, DR0, DR1);

            const float dt = cp[k + 1] - cp[k];
            float tot = (acc.x + acc.y) * (dt * factor * 0.17677669529663687f);
            #pragma unroll
            for (int off = 16; off > 0; off >>= 1)
                tot += __shfl_down_sync(0xFFFFFFFFu, tot, off);
            if (lane == 0) g_part[u * 8 + wid] = tot;

        } else if (u >= B_FLT) {
            // ---------------- flt unit (4096 edges) ----------------
            const int base = (u - B_FLT) * 4096;
            const float seg = cp[1] - cp[0];

            float acc = 0.0f;
            #pragma unroll 4
            for (int r = 0; r < 16; r++) {
                const int e = base + r * 256 + tid;
                const float t  = ts[e];
                const float q  = t / seg;
                const float kf = floorf(q);
                const int   ka = (int)kf;
                const float d  = q - kf;
                const float od = 1.0f - d;

                const float* zs = Z + snd[e] * ZSTRIDE;
                const float* zr = Z + rcv[e] * ZSTRIDE;
                const float sc0 = zs[ka],     sn0 = zs[ka + 1];
                const float sc1 = zs[9 + ka], sn1 = zs[9 + ka + 1];
                const float rc0 = zr[ka],     rn0 = zr[ka + 1];
                const float rc1 = zr[9 + ka], rn1 = zr[9 + ka + 1];

                const float scrc = sc0 * rc0 + sc1 * rc1;
                const float scsc = sc0 * sc0 + sc1 * sc1;
                const float rcrc = rc0 * rc0 + rc1 * rc1;
                const float scrn = sc0 * rn0 + sc1 * rn1;
                const float snrc = sn0 * rc0 + sn1 * rc1;
                const float scsn = sc0 * sn0 + sc1 * sn1;
                const float rcrn = rc0 * rn0 + rc1 * rn1;
                const float snrn = sn0 * rn0 + sn1 * rn1;
                const float snsn = sn0 * sn0 + sn1 * sn1;
                const float rnrn = rn0 * rn0 + rn1 * rn1;

                acc += od * od * (2.0f * scrc - scsc - rcrc)
                     + 2.0f * d * od * (scrn + snrc - scsn - rcrn)
                     + d * d * (2.0f * snrn - snsn - rnrn);
            }
            #pragma unroll
            for (int off = 16; off > 0; off >>= 1)
                acc += __shfl_down_sync(0xFFFFFFFFu, acc, off);
            if (lane == 0) g_part[u * 8 + wid] = acc;

        } else if (u == B_PRIOR) {
            // ---------------- prior unit (4096 nodes) ----------------
            float acc = 0.0f;
            #pragma unroll
            for (int r = 0; r < 16; r++) {
                const int n = nodes[r * 256 + tid];
                const float* z = Z + n * ZSTRIDE;
                #pragma unroll
                for (int dim = 0; dim < 2; dim++) {
                    const float* zd = z + dim * 9;
                    float prev = zd[0];
                    acc += prev * prev;
                    #pragma unroll
                    for (int kk = 1; kk <= 8; kk++) {
                        const float cur = zd[kk];
                        const float df  = cur - prev;
                        acc += df * df;
                        prev = cur;
                    }
                }
            }
            #pragma unroll
            for (int off = 16; off > 0; off >>= 1)
                acc += __shfl_down_sync(0xFFFFFFFFu, acc, off);
            if (lane == 0) g_part[u * 8 + wid] = acc;

        } else {
            // ---------------- prep unit: compact non-senders ----------------
            // rank(n) = #(su <= n) by binary search; if n not in su:
            // g_notS[n - rank] = n. Order-independent -> deterministic.
            #pragma unroll
            for (int r = 0; r < 4; r++) {
                const int n = u * 1024 + r * 256 + tid;
                int lo = 0, hi = N_SEND;
                while (lo < hi) {
                    const int mid = (lo + hi) >> 1;
                    if (su[mid] <= n) lo = mid + 1; else hi = mid;
                }
                const bool member = (lo > 0) && (su[lo - 1] == n);
                if (!member) g_notS[n - lo] = n;
            }
            __threadfence();
            __syncthreads();
            if (tid == 0) atomicAdd(&g_prep_flag, 1u);
        }
    }
}

// ---------------------------------------------------------------------------
// Final combine: fixed-order parallel reduction over the slot ranges,
// then scalar combine + counter/flag reset for graph replay.
// ---------------------------------------------------------------------------
__global__ void __launch_bounds__(512)
final_kernel(const float* __restrict__ beta_p, float* __restrict__ out)
{
    __shared__ float red[512];
    __shared__ float s_int, s_flt;
    const int tid = threadIdx.x;

    // integral slots [B_B*8, U_ALL*8)
    float s = 0.0f;
    for (int i = B_B * 8 + tid; i < U_ALL * 8; i += 512) s += g_part[i];
    red[tid] = s;
    __syncthreads();
    for (int st = 256; st > 0; st >>= 1) {
        if (tid < st) red[tid] += red[tid + st];
        __syncthreads();
    }
    if (tid == 0) s_int = red[0];
    __syncthreads();

    // flt slots [B_FLT*8, B_B*8) -- exactly 512
    red[tid] = g_part[B_FLT * 8 + tid];
    __syncthreads();
    for (int st = 256; st > 0; st >>= 1) {
        if (tid < st) red[tid] += red[tid + st];
        __syncthreads();
    }
    if (tid == 0) s_flt = red[0];
    __syncthreads();

    if (tid == 0) {
        float prior_raw = 0.0f;
        #pragma unroll
        for (int i = 0; i < 8; i++) prior_raw += g_part[B_PRIOR * 8 + i];

        const float beta   = beta_p[0];
        const float prior  = 10.0f * prior_raw;              // PENALTY
        const float result = 2.0f * (prior - beta * 262144.0f - s_flt
                              + 2.5066282746310002f * expf(beta) * s_int);
        out[0] = result;
        g_unit_ctr  = 0;   // reset for next graph replay
        g_prep_flag = 0;
    }
}

// ---------------------------------------------------------------------------
extern "C" void kernel_launch(void* const* d_in, const int* in_sizes, int n_in,
                              void* d_out, int out_size)
{
    const float* Z    = (const float*)d_in[0];
    const float* beta = (const float*)d_in[1];
    const float* ts   = (const float*)d_in[2];
    const int*   snd  = (const int*)d_in[3];
    const int*   rcv  = (const int*)d_in[4];
    const int*   nds  = (const int*)d_in[5];
    const int*   su   = (const int*)d_in[6];
    const float* cp   = (const float*)d_in[7];
    float* out = (float*)d_out;

    fused_kernel<<<GRID, 256>>>(Z, su, cp, ts, snd, rcv, nds);
    final_kernel<<<1, 512>>>(beta, out);
}